// round 1
// baseline (speedup 1.0000x reference)
#include <cuda_runtime.h>
#include <math.h>

// ---------------------------------------------------------------------------
// Attention_3856880632117: single-head causal attention, fp32.
//   q = x @ Wq^T ; k = x @ Wk^T ; v = x @ Wv^T          (nn.Linear semantics)
//   S = q @ k^T * C^-0.5, causal mask, softmax rows
//   out = P @ v
// Shapes: x [B=4, T=2048, C=1024]; W* [C, C]; out [B, T, C], all fp32.
//
// Stage structure (each stage independently replaceable by a tcgen05 version):
//   1) qkv_gemm   : 3 GEMMs A*B^T  (M=8192, N=1024, K=1024)
//   2) qk_gemm    : per-batch Q*K^T, lower-triangular blocks only
//   3) softmax    : causal row softmax (scale fused), zeros the block-padded tail
//   4) pv_gemm    : per-batch P*V, k-loop clipped to causal extent
// ---------------------------------------------------------------------------

#define NB 4
#define NT 2048
#define NC 1024

#define BM 128
#define BN 128
#define BK 16
#define TM 8
#define TN 8
#define NTHREADS 256   // (BM/TM)*(BN/TN)

// Scratch (allocation-free rule: __device__ globals).
__device__ float g_q[(size_t)NB * NT * NC];   // 32 MB
__device__ float g_k[(size_t)NB * NT * NC];   // 32 MB
__device__ float g_v[(size_t)NB * NT * NC];   // 32 MB
__device__ float g_s[(size_t)NB * NT * NT];   // 64 MB  (scores -> probs in place)

// ---------------------------------------------------------------------------
// Shared GEMM body. C[m0:m0+128, n0:n0+128] = A * op(B), fp32, 8x8 per thread.
// TRANSB=true : B is [N,K] row-major (compute A*B^T)
// TRANSB=false: B is [K,N] row-major (compute A*B)
// ---------------------------------------------------------------------------
template <bool TRANSB>
__device__ __forceinline__ void gemm_body(
    const float* __restrict__ A, const float* __restrict__ Bm,
    float* __restrict__ Cm,
    int lda, int ldb, int ldc, int m0, int n0, int ktiles)
{
    __shared__ float As[BK][BM + 4];
    __shared__ float Bs[BK][BN + 4];

    const int tid = threadIdx.x;
    const int tn = (tid & 15) * TN;   // col offset within tile
    const int tm = (tid >> 4) * TM;   // row offset within tile

    float acc[TM][TN] = {};

    for (int kt = 0; kt < ktiles; ++kt) {
        const int kbase = kt * BK;

        // Load A tile [BM x BK], store transposed As[k][m].
        #pragma unroll
        for (int i = 0; i < (BM * BK) / NTHREADS; ++i) {
            int idx = i * NTHREADS + tid;
            int r = idx >> 4, k = idx & 15;
            As[k][r] = A[(size_t)(m0 + r) * lda + kbase + k];
        }
        // Load B tile -> Bs[k][n].
        if (TRANSB) {
            #pragma unroll
            for (int i = 0; i < (BN * BK) / NTHREADS; ++i) {
                int idx = i * NTHREADS + tid;
                int r = idx >> 4, k = idx & 15;
                Bs[k][r] = Bm[(size_t)(n0 + r) * ldb + kbase + k];
            }
        } else {
            #pragma unroll
            for (int i = 0; i < (BN * BK) / NTHREADS; ++i) {
                int idx = i * NTHREADS + tid;
                int n = idx & (BN - 1), k = idx >> 7;
                Bs[k][n] = Bm[(size_t)(kbase + k) * ldb + n0 + n];
            }
        }
        __syncthreads();

        #pragma unroll
        for (int kk = 0; kk < BK; ++kk) {
            float a[TM], bv[TN];
            #pragma unroll
            for (int i = 0; i < TM; ++i) a[i] = As[kk][tm + i];
            #pragma unroll
            for (int j = 0; j < TN; ++j) bv[j] = Bs[kk][tn + j];
            #pragma unroll
            for (int i = 0; i < TM; ++i)
                #pragma unroll
                for (int j = 0; j < TN; ++j)
                    acc[i][j] = fmaf(a[i], bv[j], acc[i][j]);
        }
        __syncthreads();
    }

    // Store 8x8 per thread as 2x float4 per row.
    #pragma unroll
    for (int i = 0; i < TM; ++i) {
        float4* p = reinterpret_cast<float4*>(
            &Cm[(size_t)(m0 + tm + i) * ldc + n0 + tn]);
        p[0] = make_float4(acc[i][0], acc[i][1], acc[i][2], acc[i][3]);
        p[1] = make_float4(acc[i][4], acc[i][5], acc[i][6], acc[i][7]);
    }
}

// Stage 1: fused QKV projections. grid = (NC/BN, (NB*NT)/BM, 3)
__global__ __launch_bounds__(NTHREADS, 2)
void qkv_gemm(const float* __restrict__ x,
              const float* __restrict__ Wq,
              const float* __restrict__ Wk,
              const float* __restrict__ Wv)
{
    const float* W = (blockIdx.z == 0) ? Wq : (blockIdx.z == 1) ? Wk : Wv;
    float* out     = (blockIdx.z == 0) ? g_q : (blockIdx.z == 1) ? g_k : g_v;
    gemm_body<true>(x, W, out,
                    NC, NC, NC,
                    blockIdx.y * BM, blockIdx.x * BN, NC / BK);
}

// Stage 2: S = Q*K^T per batch, lower-triangular blocks only.
// grid = (NT/BN, NT/BM, NB)
__global__ __launch_bounds__(NTHREADS, 2)
void qk_gemm()
{
    if (blockIdx.x > blockIdx.y) return;  // fully-masked block: softmax never reads it
    const size_t boff = (size_t)blockIdx.z * NT * NC;
    gemm_body<true>(g_q + boff, g_k + boff,
                    g_s + (size_t)blockIdx.z * NT * NT,
                    NC, NC, NT,
                    blockIdx.y * BM, blockIdx.x * BN, NC / BK);
}

// Stage 3: causal row softmax with scale fused; zero-pads up to the next
// 128-row block boundary so pv_gemm can read full k-tiles.
// grid = (NT, NB), 256 threads
__global__ __launch_bounds__(NTHREADS)
void softmax_causal(float scale)
{
    const int i = blockIdx.x;
    float* row = g_s + ((size_t)blockIdx.y * NT + i) * NT;
    const int len = i + 1;
    const int tid = threadIdx.x;
    const int lane = tid & 31, warp = tid >> 5;

    __shared__ float sh[8];
    __shared__ float s_bcast;

    // --- max over [0, len) ---
    float m = -INFINITY;
    for (int j = tid; j < len; j += NTHREADS) m = fmaxf(m, row[j]);
    #pragma unroll
    for (int o = 16; o > 0; o >>= 1) m = fmaxf(m, __shfl_xor_sync(0xffffffffu, m, o));
    if (lane == 0) sh[warp] = m;
    __syncthreads();
    if (tid < 32) {
        float v = (lane < 8) ? sh[lane] : -INFINITY;
        #pragma unroll
        for (int o = 4; o > 0; o >>= 1) v = fmaxf(v, __shfl_xor_sync(0xffffffffu, v, o));
        if (lane == 0) s_bcast = v;
    }
    __syncthreads();
    m = s_bcast;
    __syncthreads();

    // --- exp + sum ---
    float s = 0.0f;
    for (int j = tid; j < len; j += NTHREADS) {
        float e = __expf((row[j] - m) * scale);
        row[j] = e;
        s += e;
    }
    #pragma unroll
    for (int o = 16; o > 0; o >>= 1) s += __shfl_xor_sync(0xffffffffu, s, o);
    if (lane == 0) sh[warp] = s;
    __syncthreads();
    if (tid < 32) {
        float v = (lane < 8) ? sh[lane] : 0.0f;
        #pragma unroll
        for (int o = 4; o > 0; o >>= 1) v += __shfl_xor_sync(0xffffffffu, v, o);
        if (lane == 0) s_bcast = v;
    }
    __syncthreads();
    const float inv = 1.0f / s_bcast;

    // --- normalize, and zero the tail up to the block boundary ---
    const int jend = ((i >> 7) + 1) << 7;   // next multiple of 128
    for (int j = tid; j < jend; j += NTHREADS)
        row[j] = (j < len) ? row[j] * inv : 0.0f;
}

// Stage 4: O = P*V per batch, k-loop clipped to causal extent.
// grid = (NC/BN, NT/BM, NB)
__global__ __launch_bounds__(NTHREADS, 2)
void pv_gemm(float* __restrict__ out)
{
    const int by = blockIdx.y;
    const int ktiles = ((by + 1) * BM) / BK;   // s <= row block's max t
    gemm_body<false>(g_s + (size_t)blockIdx.z * NT * NT,
                     g_v + (size_t)blockIdx.z * NT * NC,
                     out + (size_t)blockIdx.z * NT * NC,
                     NT, NC, NC,
                     by * BM, blockIdx.x * BN, ktiles);
}

extern "C" void kernel_launch(void* const* d_in, const int* in_sizes, int n_in,
                              void* d_out, int out_size)
{
    const float* x  = (const float*)d_in[0];
    const float* Wq = (const float*)d_in[1];
    const float* Wk = (const float*)d_in[2];
    const float* Wv = (const float*)d_in[3];
    float* out = (float*)d_out;

    dim3 blk(NTHREADS);

    qkv_gemm<<<dim3(NC / BN, (NB * NT) / BM, 3), blk>>>(x, Wq, Wk, Wv);
    qk_gemm<<<dim3(NT / BN, NT / BM, NB), blk>>>();
    softmax_causal<<<dim3(NT, NB), blk>>>(1.0f / 32.0f);   // C^-0.5 = 1024^-0.5
    pv_gemm<<<dim3(NC / BN, NT / BM, NB), blk>>>(out);
}

// round 3
// speedup vs baseline: 3.4175x; 3.4175x over previous
#include <cuda_runtime.h>
#include <cstdint>
#include <math.h>

// ---------------------------------------------------------------------------
// Attention_3856880632117 — mma.sync (bf16, 2-term split) implementation.
// ptxas target here is plain sm_103 (no 'a'), so tcgen05 is unavailable;
// tensor cores are reached via baseline mma.sync.m16n8k16.bf16 + ldmatrix.
//
//   Stage 1: q = x Wq^T, k = x Wk^T, vt = Wv x^T  ([C][B*T] layout)
//   Stage 2: S = q k^T (lower-triangular tiles only)
//   Stage 3: causal softmax (scale fused, zero-padded to 128 boundary)
//   Stage 4: out = P vt^T (k-extent clipped to causal extent)
// All GEMMs: C = A * B^T, A[M,K] row-major, B[N,K] row-major, fp32 I/O.
// fp32-ish accuracy: x = hi + lo (bf16); C += Ah*Bh + Ah*Bl + Al*Bh.
// ---------------------------------------------------------------------------

#define NB 4
#define NT 2048
#define NCH 1024

// Scratch (allocation-free rule: __device__ globals).
__device__ float g_q [(size_t)NB * NT * NCH];    // 32 MB
__device__ float g_k [(size_t)NB * NT * NCH];    // 32 MB
__device__ float g_vt[(size_t)NCH * NB * NT];    // 32 MB, layout [c][b*T + t]
__device__ float g_s [(size_t)NB * NT * NT];     // 64 MB (scores -> probs)

// ---------------- tensor-core primitives (baseline PTX, no *_a) ------------
__device__ __forceinline__ void ldsm4(uint32_t* r, uint32_t addr) {
    asm volatile("ldmatrix.sync.aligned.m8n8.x4.shared.b16 {%0,%1,%2,%3}, [%4];"
                 : "=r"(r[0]), "=r"(r[1]), "=r"(r[2]), "=r"(r[3]) : "r"(addr));
}
__device__ __forceinline__ void mma_bf16(float* c, const uint32_t* a, const uint32_t* b) {
    asm volatile(
        "mma.sync.aligned.m16n8k16.row.col.f32.bf16.bf16.f32 "
        "{%0,%1,%2,%3},{%4,%5,%6,%7},{%8,%9},{%0,%1,%2,%3};"
        : "+f"(c[0]), "+f"(c[1]), "+f"(c[2]), "+f"(c[3])
        : "r"(a[0]), "r"(a[1]), "r"(a[2]), "r"(a[3]), "r"(b[0]), "r"(b[1]));
}
__device__ __forceinline__ uint32_t smem_u32(const void* p) {
    uint32_t a;
    asm("{ .reg .u64 t; cvta.to.shared.u64 t, %1; cvt.u32.u64 %0, t; }"
        : "=r"(a) : "l"(p));
    return a;
}
// pack two fp32 -> bf16x2 (lo operand lands in low 16 bits)
__device__ __forceinline__ uint32_t pack_bf16x2(float hi, float lo) {
    uint32_t r;
    asm("cvt.rn.bf16x2.f32 %0, %1, %2;" : "=r"(r) : "f"(hi), "f"(lo));
    return r;
}

// ---------------------------------------------------------------------------
// SMEM geometry: bf16 tiles 128 rows x 32 cols, row pitch 40 elems (80 B).
// Regions per stage: Ahi | Alo | Bhi | Blo, 10240 B each; 2 stages.
// 80 B row stride => ldmatrix 8-row wavefronts hit all 32 banks exactly once.
// ---------------------------------------------------------------------------
#define PITCHB     80
#define REGION     10240
#define STAGE_B    40960
#define SMEM_TOTAL (2 * STAGE_B)

__device__ __forceinline__ void mma_gemm_tile(
    const float* __restrict__ At, int lda,   // A tile base (row 0 of this tile)
    const float* __restrict__ Bt, int ldb,   // B tile base
    float* __restrict__ Ct, int ldc,         // C tile base
    int nch)                                  // number of K chunks of 32
{
    extern __shared__ char smraw[];
    char* sm = smraw;
    const uint32_t smu = smem_u32(sm);

    const int tid  = threadIdx.x;
    const int lane = tid & 31;
    const int wid  = tid >> 5;
    const int wm   = wid >> 2;   // 0..1  (64 rows each)
    const int wn   = wid & 3;    // 0..3  (32 cols each)

    // gmem load coords: 4 float4 per thread per tile (A and B each)
    const int ldr = tid >> 3;          // 0..31 (+32*i)
    const int ldc4 = tid & 7;          // float4 group within 32-float row

    // ldmatrix per-lane constant offsets
    const uint32_t aRowByte = (uint32_t)(lane & 15) * PITCHB + (uint32_t)(lane >> 4) * 16;
    const uint32_t bRowByte = (uint32_t)(((lane >> 4) << 3) + (lane & 7)) * PITCHB
                            + (uint32_t)((lane >> 3) & 1) * 16;

    float acc[4][4][4];
    #pragma unroll
    for (int mf = 0; mf < 4; ++mf)
        #pragma unroll
        for (int nf = 0; nf < 4; ++nf)
            #pragma unroll
            for (int q = 0; q < 4; ++q) acc[mf][nf][q] = 0.0f;

    float4 pa[4], pb[4];

    auto ldg_chunk = [&](int kt) {
        const int kb = kt * 32;
        #pragma unroll
        for (int i = 0; i < 4; ++i) {
            int r = ldr + i * 32;
            pa[i] = *reinterpret_cast<const float4*>(At + (size_t)r * lda + kb + ldc4 * 4);
            pb[i] = *reinterpret_cast<const float4*>(Bt + (size_t)r * ldb + kb + ldc4 * 4);
        }
    };

    auto cvt_sts = [&](int buf) {
        char* base = sm + buf * STAGE_B;
        #pragma unroll
        for (int i = 0; i < 4; ++i) {
            int r = ldr + i * 32;
            uint32_t off = (uint32_t)r * PITCHB + (uint32_t)ldc4 * 8;
            {   // A
                float4 v = pa[i];
                uint32_t h01 = pack_bf16x2(v.y, v.x);
                uint32_t h23 = pack_bf16x2(v.w, v.z);
                float hx = __uint_as_float(h01 << 16);
                float hy = __uint_as_float(h01 & 0xFFFF0000u);
                float hz = __uint_as_float(h23 << 16);
                float hw = __uint_as_float(h23 & 0xFFFF0000u);
                uint32_t l01 = pack_bf16x2(v.y - hy, v.x - hx);
                uint32_t l23 = pack_bf16x2(v.w - hw, v.z - hz);
                *reinterpret_cast<uint2*>(base + off)          = make_uint2(h01, h23);
                *reinterpret_cast<uint2*>(base + REGION + off) = make_uint2(l01, l23);
            }
            {   // B
                float4 v = pb[i];
                uint32_t h01 = pack_bf16x2(v.y, v.x);
                uint32_t h23 = pack_bf16x2(v.w, v.z);
                float hx = __uint_as_float(h01 << 16);
                float hy = __uint_as_float(h01 & 0xFFFF0000u);
                float hz = __uint_as_float(h23 << 16);
                float hw = __uint_as_float(h23 & 0xFFFF0000u);
                uint32_t l01 = pack_bf16x2(v.y - hy, v.x - hx);
                uint32_t l23 = pack_bf16x2(v.w - hw, v.z - hz);
                *reinterpret_cast<uint2*>(base + 2 * REGION + off) = make_uint2(h01, h23);
                *reinterpret_cast<uint2*>(base + 3 * REGION + off) = make_uint2(l01, l23);
            }
        }
    };

    auto mma_chunk = [&](int buf) {
        const uint32_t sbase = smu + (uint32_t)buf * STAGE_B;
        #pragma unroll
        for (int sk = 0; sk < 2; ++sk) {
            uint32_t ah[4][4], al[4][4], bh[4][2], bl[4][2];
            const uint32_t aBase = sbase + (uint32_t)(wm * 64) * PITCHB + aRowByte
                                 + (uint32_t)sk * 32;
            #pragma unroll
            for (int mf = 0; mf < 4; ++mf) {
                ldsm4(ah[mf], aBase + (uint32_t)mf * (16 * PITCHB));
                ldsm4(al[mf], aBase + (uint32_t)mf * (16 * PITCHB) + REGION);
            }
            const uint32_t bBase = sbase + 2 * REGION + (uint32_t)(wn * 32) * PITCHB
                                 + bRowByte + (uint32_t)sk * 32;
            #pragma unroll
            for (int p = 0; p < 2; ++p) {
                uint32_t t[4];
                ldsm4(t, bBase + (uint32_t)p * (16 * PITCHB));
                bh[2 * p][0] = t[0]; bh[2 * p][1] = t[1];
                bh[2 * p + 1][0] = t[2]; bh[2 * p + 1][1] = t[3];
                ldsm4(t, bBase + (uint32_t)p * (16 * PITCHB) + REGION);
                bl[2 * p][0] = t[0]; bl[2 * p][1] = t[1];
                bl[2 * p + 1][0] = t[2]; bl[2 * p + 1][1] = t[3];
            }
            #pragma unroll
            for (int mf = 0; mf < 4; ++mf)
                #pragma unroll
                for (int nf = 0; nf < 4; ++nf)
                    mma_bf16(acc[mf][nf], ah[mf], bh[nf]);
            #pragma unroll
            for (int mf = 0; mf < 4; ++mf)
                #pragma unroll
                for (int nf = 0; nf < 4; ++nf)
                    mma_bf16(acc[mf][nf], ah[mf], bl[nf]);
            #pragma unroll
            for (int mf = 0; mf < 4; ++mf)
                #pragma unroll
                for (int nf = 0; nf < 4; ++nf)
                    mma_bf16(acc[mf][nf], al[mf], bh[nf]);
        }
    };

    // pipeline: LDG(kt+1) in flight while MMA(kt) runs
    ldg_chunk(0);
    cvt_sts(0);
    __syncthreads();
    for (int kt = 0; kt < nch; ++kt) {
        const bool more = (kt + 1 < nch);
        if (more) ldg_chunk(kt + 1);
        mma_chunk(kt & 1);
        if (more) {
            cvt_sts((kt + 1) & 1);
            __syncthreads();
        }
    }

    // epilogue
    #pragma unroll
    for (int mf = 0; mf < 4; ++mf) {
        #pragma unroll
        for (int nf = 0; nf < 4; ++nf) {
            int row = wm * 64 + mf * 16 + (lane >> 2);
            int col = wn * 32 + nf * 8 + (lane & 3) * 2;
            float* p0 = Ct + (size_t)row * ldc + col;
            float* p1 = Ct + (size_t)(row + 8) * ldc + col;
            *reinterpret_cast<float2*>(p0) = make_float2(acc[mf][nf][0], acc[mf][nf][1]);
            *reinterpret_cast<float2*>(p1) = make_float2(acc[mf][nf][2], acc[mf][nf][3]);
        }
    }
}

// Stage 1: QKV. grid = (64, 8, 3). z<2: m-tile = x (of 8192), n-tile = y (of 1024).
// z==2 computes vt = Wv * x^T: m-tile = y (of 1024 rows c), n-tile = x (of 8192 cols t).
__global__ __launch_bounds__(256, 1)
void qkv_mma(const float* __restrict__ x,
             const float* __restrict__ Wq,
             const float* __restrict__ Wk,
             const float* __restrict__ Wv)
{
    const int bx = blockIdx.x, by = blockIdx.y, z = blockIdx.z;
    if (z == 0) {
        mma_gemm_tile(x + (size_t)bx * 128 * NCH, NCH,
                      Wq + (size_t)by * 128 * NCH, NCH,
                      g_q + (size_t)bx * 128 * NCH + by * 128, NCH, NCH / 32);
    } else if (z == 1) {
        mma_gemm_tile(x + (size_t)bx * 128 * NCH, NCH,
                      Wk + (size_t)by * 128 * NCH, NCH,
                      g_k + (size_t)bx * 128 * NCH + by * 128, NCH, NCH / 32);
    } else {
        mma_gemm_tile(Wv + (size_t)by * 128 * NCH, NCH,
                      x + (size_t)bx * 128 * NCH, NCH,
                      g_vt + (size_t)by * 128 * (NB * NT) + bx * 128, NB * NT, NCH / 32);
    }
}

// Stage 2: S = Q K^T, lower-triangular tiles. grid = (16, 16, NB)
__global__ __launch_bounds__(256, 1)
void qk_mma()
{
    if (blockIdx.x > blockIdx.y) return;
    const int b = blockIdx.z;
    mma_gemm_tile(g_q + (size_t)b * NT * NCH + (size_t)blockIdx.y * 128 * NCH, NCH,
                  g_k + (size_t)b * NT * NCH + (size_t)blockIdx.x * 128 * NCH, NCH,
                  g_s + (size_t)b * NT * NT + (size_t)blockIdx.y * 128 * NT
                      + blockIdx.x * 128, NT, NCH / 32);
}

// Stage 3: causal row softmax (scale fused), zero-pads to 128 boundary.
__global__ __launch_bounds__(256)
void softmax_causal(float scale)
{
    const int i = blockIdx.x;
    float* row = g_s + ((size_t)blockIdx.y * NT + i) * NT;
    const int len = i + 1;
    const int tid = threadIdx.x;
    const int lane = tid & 31, warp = tid >> 5;

    __shared__ float sh[8];
    __shared__ float s_bcast;

    float m = -INFINITY;
    for (int j = tid; j < len; j += 256) m = fmaxf(m, row[j]);
    #pragma unroll
    for (int o = 16; o > 0; o >>= 1) m = fmaxf(m, __shfl_xor_sync(0xffffffffu, m, o));
    if (lane == 0) sh[warp] = m;
    __syncthreads();
    if (tid < 32) {
        float v = (lane < 8) ? sh[lane] : -INFINITY;
        #pragma unroll
        for (int o = 4; o > 0; o >>= 1) v = fmaxf(v, __shfl_xor_sync(0xffffffffu, v, o));
        if (lane == 0) s_bcast = v;
    }
    __syncthreads();
    m = s_bcast;
    __syncthreads();

    float s = 0.0f;
    for (int j = tid; j < len; j += 256) {
        float e = __expf((row[j] - m) * scale);
        row[j] = e;
        s += e;
    }
    #pragma unroll
    for (int o = 16; o > 0; o >>= 1) s += __shfl_xor_sync(0xffffffffu, s, o);
    if (lane == 0) sh[warp] = s;
    __syncthreads();
    if (tid < 32) {
        float v = (lane < 8) ? sh[lane] : 0.0f;
        #pragma unroll
        for (int o = 4; o > 0; o >>= 1) v += __shfl_xor_sync(0xffffffffu, v, o);
        if (lane == 0) s_bcast = v;
    }
    __syncthreads();
    const float inv = 1.0f / s_bcast;

    const int jend = ((i >> 7) + 1) << 7;
    for (int j = tid; j < jend; j += 256)
        row[j] = (j < len) ? row[j] * inv : 0.0f;
}

// Stage 4: out = P * vt^T, k-extent clipped. grid = (8, 16, NB)
__global__ __launch_bounds__(256, 1)
void pv_mma(float* __restrict__ out)
{
    const int b = blockIdx.z, by = blockIdx.y, bx = blockIdx.x;
    mma_gemm_tile(g_s + (size_t)b * NT * NT + (size_t)by * 128 * NT, NT,
                  g_vt + (size_t)bx * 128 * (NB * NT) + (size_t)b * NT, NB * NT,
                  out + (size_t)b * NT * NCH + (size_t)by * 128 * NCH + bx * 128, NCH,
                  (by + 1) * 4);
}

extern "C" void kernel_launch(void* const* d_in, const int* in_sizes, int n_in,
                              void* d_out, int out_size)
{
    const float* x  = (const float*)d_in[0];
    const float* Wq = (const float*)d_in[1];
    const float* Wk = (const float*)d_in[2];
    const float* Wv = (const float*)d_in[3];
    float* out = (float*)d_out;

    static bool attr_done = false;
    if (!attr_done) {
        cudaFuncSetAttribute(qkv_mma, cudaFuncAttributeMaxDynamicSharedMemorySize, SMEM_TOTAL);
        cudaFuncSetAttribute(qk_mma,  cudaFuncAttributeMaxDynamicSharedMemorySize, SMEM_TOTAL);
        cudaFuncSetAttribute(pv_mma,  cudaFuncAttributeMaxDynamicSharedMemorySize, SMEM_TOTAL);
        attr_done = true;
    }

    dim3 blk(256);
    qkv_mma<<<dim3(64, 8, 3), blk, SMEM_TOTAL>>>(x, Wq, Wk, Wv);
    qk_mma<<<dim3(16, 16, NB), blk, SMEM_TOTAL>>>();
    softmax_causal<<<dim3(NT, NB), blk>>>(1.0f / 32.0f);   // 1024^-0.5
    pv_mma<<<dim3(8, 16, NB), blk, SMEM_TOTAL>>>(out);
}